// round 9
// baseline (speedup 1.0000x reference)
#include <cuda_runtime.h>
#include <math.h>

// Problem constants
constexpr int Bc = 8;
constexpr int Cc = 64;
constexpr int Nc = 4096;
constexpr int Kc = 20;
constexpr int Oc = 64;
constexpr float BN_EPS = 1e-5f;
constexpr float NEG_SLOPE = 0.2f;
constexpr float FLT_BIG = 3.4e38f;

constexpr int QB  = 64;      // queries per block (knn)
constexpr int TJ  = 128;     // candidate tile size
constexpr int AP  = 68;      // As row pad (floats)
constexpr int BP  = 132;     // Bs row pad (floats)
constexpr int NT  = 256;     // threads per block (knn)

// -------------------- device scratch (no allocations allowed) --------------------
__device__ float  g_xx[Bc * Nc];            // squared norms
__device__ int    g_idx[Bc * Nc * Kc];      // knn indices
__device__ float  g_P[Bc * Nc * Oc];        // W1 . x_j projection
__device__ float  g_Q[Bc * Nc * Oc];        // (W2-W1) . x_i projection
__device__ float  g_mx[Bc * Nc * Oc];       // max_k h
__device__ float  g_mn[Bc * Nc * Oc];       // min_k h
__device__ double g_sum[Oc];
__device__ double g_sumsq[Oc];
__device__ float  g_scale[Oc];
__device__ float  g_shift[Oc];
__device__ float  g_W1t[Cc * Oc];
__device__ float  g_Wdt[Cc * Oc];

// -------------------- f32x2 packed helpers --------------------
typedef unsigned long long u64;
typedef unsigned int u32;
__device__ __forceinline__ u64 dup2(float v) {
    u64 r; asm("mov.b64 %0, {%1, %1};" : "=l"(r) : "f"(v)); return r;
}
__device__ __forceinline__ void ffma2(u64& d, u64 a, u64 b) {
    asm("fma.rn.f32x2 %0, %1, %2, %0;" : "+l"(d) : "l"(a), "l"(b));
}
__device__ __forceinline__ u64 fma2o(u64 a, u64 b, u64 c) {
    u64 r; asm("fma.rn.f32x2 %0, %1, %2, %3;" : "=l"(r) : "l"(a), "l"(b), "l"(c));
    return r;
}
__device__ __forceinline__ u64 add2(u64 a, u64 b) {
    u64 r; asm("add.rn.f32x2 %0, %1, %2;" : "=l"(r) : "l"(a), "l"(b));
    return r;
}
__device__ __forceinline__ void unpack2(u64 v, float& lo, float& hi) {
    asm("mov.b64 {%0, %1}, %2;" : "=f"(lo), "=f"(hi) : "l"(v));
}
// orderable float mapping: monotonic uint32 key (handles negatives)
__device__ __forceinline__ u32 ordf(float f) {
    u32 u = __float_as_uint(f);
    return (u & 0x80000000u) ? ~u : (u | 0x80000000u);
}
__device__ __forceinline__ float inv_ordf(u32 v) {
    u32 u = (v & 0x80000000u) ? (v & 0x7FFFFFFFu) : ~v;
    return __uint_as_float(u);
}

constexpr u64 KEY_MAX = 0xFFFFFFFFFFFFFFFFull;

// -------------------- kernel: squared norms --------------------
__global__ void k_xx(const float* __restrict__ x) {
    int t = blockIdx.x * blockDim.x + threadIdx.x;    // over B*N
    int b = t >> 12;
    int n = t & (Nc - 1);
    const float* xb = x + (size_t)b * Cc * Nc + n;
    float s = 0.f;
#pragma unroll
    for (int c = 0; c < Cc; ++c) {
        float v = xb[c * Nc];
        s = fmaf(v, v, s);
    }
    g_xx[t] = s;
}

// -------------------- kernel: prep W transposes + zero stats --------------------
__global__ void k_prep(const float* __restrict__ W) {
    int t = blockIdx.x * blockDim.x + threadIdx.x;
    if (t < Cc * Oc) {
        int c = t & 63;
        int o = t >> 6;
        float w1 = W[o * (2 * Cc) + c];
        float w2 = W[o * (2 * Cc) + Cc + c];
        g_W1t[c * Oc + o] = w1;
        g_Wdt[c * Oc + o] = w2 - w1;
    }
    if (blockIdx.x == 0 && t < Oc) {
        g_sum[t] = 0.0;
        g_sumsq[t] = 0.0;
    }
}

// -------------------- kernel: P and Q projections --------------------
__global__ void __launch_bounds__(256) k_pq(const float* __restrict__ x) {
    int b  = blockIdx.y;
    int n0 = blockIdx.x * 32;
    int o  = threadIdx.x & 63;
    int gg = threadIdx.x >> 6;
    __shared__ float xs[Cc][36];

    for (int t = threadIdx.x; t < Cc * 32; t += 256) {
        int nn = t & 31;
        int c  = t >> 5;
        xs[c][nn] = x[(size_t)b * Cc * Nc + c * Nc + n0 + nn];
    }
    __syncthreads();

    float ap[8], aq[8];
#pragma unroll
    for (int r = 0; r < 8; ++r) { ap[r] = 0.f; aq[r] = 0.f; }
    const int nbase = gg * 8;

#pragma unroll 8
    for (int c = 0; c < Cc; ++c) {
        float w1 = __ldg(&g_W1t[c * Oc + o]);
        float wd = __ldg(&g_Wdt[c * Oc + o]);
        float4 v0 = *(const float4*)&xs[c][nbase];
        float4 v1 = *(const float4*)&xs[c][nbase + 4];
        ap[0] = fmaf(w1, v0.x, ap[0]); aq[0] = fmaf(wd, v0.x, aq[0]);
        ap[1] = fmaf(w1, v0.y, ap[1]); aq[1] = fmaf(wd, v0.y, aq[1]);
        ap[2] = fmaf(w1, v0.z, ap[2]); aq[2] = fmaf(wd, v0.z, aq[2]);
        ap[3] = fmaf(w1, v0.w, ap[3]); aq[3] = fmaf(wd, v0.w, aq[3]);
        ap[4] = fmaf(w1, v1.x, ap[4]); aq[4] = fmaf(wd, v1.x, aq[4]);
        ap[5] = fmaf(w1, v1.y, ap[5]); aq[5] = fmaf(wd, v1.y, aq[5]);
        ap[6] = fmaf(w1, v1.z, ap[6]); aq[6] = fmaf(wd, v1.z, aq[6]);
        ap[7] = fmaf(w1, v1.w, ap[7]); aq[7] = fmaf(wd, v1.w, aq[7]);
    }

    int row0 = b * Nc + n0 + nbase;
#pragma unroll
    for (int r = 0; r < 8; ++r) {
        g_P[(size_t)(row0 + r) * Oc + o] = ap[r];
        g_Q[(size_t)(row0 + r) * Oc + o] = aq[r];
    }
}

// -------------------- warp-local top-K insert (ballot + serialized rare inserts) ----
__device__ __forceinline__ void topk_warp(
    int ql, const float d[4], int jbase, int lane, u64* keys, float* wf)
{
    float w = wf[ql];
    bool any = (d[0] < w) | (d[1] < w) | (d[2] < w) | (d[3] < w);
    if (!__ballot_sync(0xFFFFFFFFu, any)) return;   // warp-uniform fast path

#pragma unroll
    for (int s = 0; s < 4; ++s) {
        unsigned m = __ballot_sync(0xFFFFFFFFu, d[s] < w);
        while (m) {
            int src = __ffs(m) - 1;
            if (lane == src) {
                u64 key = ((u64)ordf(d[s]) << 32) | (u32)(jbase + lane * 4 + s);
                if (key < keys[19 * QB + ql]) {
                    int p = Kc - 1;
                    while (p > 0 && keys[(p - 1) * QB + ql] > key) {
                        keys[p * QB + ql] = keys[(p - 1) * QB + ql];
                        --p;
                    }
                    keys[p * QB + ql] = key;
                    u32 hi = (u32)(keys[19 * QB + ql] >> 32);
                    wf[ql] = (hi == 0xFFFFFFFFu) ? FLT_BIG : inv_ordf(hi);
                }
            }
            __syncwarp();
            w = wf[ql];
            m &= m - 1;
        }
    }
}

// -------------------- kernel: KNN v8 — warp-owned queries, warp-local top-k ------
// grid = (N/64, B) = 512 blocks, 256 threads, smem 62 KB -> 3 blocks/SM (24 warps).
// Warp w owns 8 queries (qw = w*8, 4 packed f32x2 pairs read broadcast from As);
// lane owns 4 j (LDS.128 from Bs). 16 FFMA2 + 3 LDS + 4 dup-MOVs per c-step.
// Distances never leave the warp: ballot-filtered inserts into shared keys.
__global__ void __launch_bounds__(NT, 3) k_knn8(const float* __restrict__ x) {
    extern __shared__ float sm[];
    u64*   keys = (u64*)sm;                 // [Kc][QB]
    float* As   = sm + Kc * QB * 2;         // [Cc][AP]
    float* Bs   = As + Cc * AP;             // [Cc][BP]
    float* sxxi = Bs + Cc * BP;             // [QB]
    float* sxxj = sxxi + QB;                // [TJ]
    float* wf   = sxxj + TJ;                // [QB]

    const int tid  = threadIdx.x;
    const int lane = tid & 31;
    const int wid  = tid >> 5;              // 8 warps
    const int qw   = wid * 8;               // first local query of this warp
    const int b    = blockIdx.y;
    const int i0   = blockIdx.x * QB;
    const float* xb = x + (size_t)b * Cc * Nc;

    // load A tile: As[c][q] = x[b][c][i0+q]
    {
        int col = (tid & 15) * 4;
        int cb  = tid >> 4;
#pragma unroll
        for (int cc = 0; cc < 4; ++cc) {
            int c = cb + cc * 16;
            float4 v = *(const float4*)&xb[(size_t)c * Nc + i0 + col];
            *(float4*)&As[c * AP + col] = v;
        }
    }
    if (tid < QB) {
        sxxi[tid] = g_xx[b * Nc + i0 + tid];
        wf[tid]   = FLT_BIG;
    }
    for (int t = tid; t < Kc * QB; t += NT) keys[t] = KEY_MAX;
    __syncthreads();

    // packed query norms for this warp's 4 pairs (broadcast)
    u64 xqp[4];
#pragma unroll
    for (int ip = 0; ip < 4; ++ip) xqp[ip] = *(const u64*)&sxxi[qw + 2 * ip];
    const u64 neg2 = dup2(-2.f);

    for (int t = 0; t < Nc / TJ; ++t) {
        const int j0 = t * TJ;

        // load B tile: Bs[c][j] = x[b][c][j0+j]
        {
            int col = (tid & 31) * 4;
            int cb  = tid >> 5;
#pragma unroll
            for (int cc = 0; cc < 8; ++cc) {
                int c = cb + cc * 8;
                float4 v = *(const float4*)&xb[(size_t)c * Nc + j0 + col];
                *(float4*)&Bs[c * BP + col] = v;
            }
        }
        if (tid < TJ) sxxj[tid] = g_xx[b * Nc + j0 + tid];
        __syncthreads();   // B ready

        // ---- GEMM: 8 queries (4 pairs, broadcast) x 4 j (lane) over c ----
        u64 acc[4][4];
#pragma unroll
        for (int ip = 0; ip < 4; ++ip)
#pragma unroll
            for (int s = 0; s < 4; ++s) acc[ip][s] = 0ULL;

#pragma unroll 8
        for (int c = 0; c < Cc; ++c) {
            ulonglong2 a01 = *(const ulonglong2*)&As[c * AP + qw];
            ulonglong2 a23 = *(const ulonglong2*)&As[c * AP + qw + 4];
            float4 bv = *(const float4*)&Bs[c * BP + lane * 4];
            u64 b0 = dup2(bv.x), b1 = dup2(bv.y), b2 = dup2(bv.z), b3 = dup2(bv.w);
            u64 a0 = a01.x, a1 = a01.y, a2 = a23.x, a3 = a23.y;
            ffma2(acc[0][0], a0, b0); ffma2(acc[1][0], a1, b0);
            ffma2(acc[2][0], a2, b0); ffma2(acc[3][0], a3, b0);
            ffma2(acc[0][1], a0, b1); ffma2(acc[1][1], a1, b1);
            ffma2(acc[2][1], a2, b1); ffma2(acc[3][1], a3, b1);
            ffma2(acc[0][2], a0, b2); ffma2(acc[1][2], a1, b2);
            ffma2(acc[2][2], a2, b2); ffma2(acc[3][2], a3, b2);
            ffma2(acc[0][3], a0, b3); ffma2(acc[1][3], a1, b3);
            ffma2(acc[2][3], a2, b3); ffma2(acc[3][3], a3, b3);
        }

        // epilogue + warp-local top-k (distances never leave the warp)
        float4 xjv = *(const float4*)&sxxj[lane * 4];
        float xjs[4] = {xjv.x, xjv.y, xjv.z, xjv.w};
#pragma unroll
        for (int ip = 0; ip < 4; ++ip) {
            float dlo[4], dhi[4];
#pragma unroll
            for (int s = 0; s < 4; ++s) {
                u64 xjd = dup2(xjs[s]);
                u64 d2  = fma2o(acc[ip][s], neg2, add2(xqp[ip], xjd));
                unpack2(d2, dlo[s], dhi[s]);
            }
            topk_warp(qw + 2 * ip,     dlo, j0, lane, keys, wf);
            topk_warp(qw + 2 * ip + 1, dhi, j0, lane, keys, wf);
        }
        __syncthreads();   // all warps done with Bs before next tile load
    }

    // write out (keys already exact sorted top-K per query)
    if (tid < QB) {
        int* op = &g_idx[((size_t)(b * Nc + i0 + tid)) * Kc];
#pragma unroll
        for (int kk = 0; kk < Kc; ++kk)
            op[kk] = (int)(u32)(keys[kk * QB + tid] & 0xFFFFFFFFull);
    }
}

// -------------------- kernel: gather + max/min + BN stats --------------------
__global__ void __launch_bounds__(256) k_edge() {
    int o  = threadIdx.x & 63;
    int gg = threadIdx.x >> 6;
    float s1 = 0.f, s2v = 0.f;

    for (int row = blockIdx.x * 4 + gg; row < Bc * Nc; row += gridDim.x * 4) {
        int b  = row >> 12;
        int nb = b << 12;
        float qv = g_Q[(size_t)row * Oc + o];
        const int* ip = &g_idx[(size_t)row * Kc];
        float mx = -FLT_BIG, mn = FLT_BIG;
#pragma unroll
        for (int kk = 0; kk < Kc; ++kk) {
            int j = __ldg(&ip[kk]);
            float h = g_P[(size_t)(nb + j) * Oc + o] + qv;
            mx = fmaxf(mx, h);
            mn = fminf(mn, h);
            s1 += h;
            s2v = fmaf(h, h, s2v);
        }
        g_mx[(size_t)row * Oc + o] = mx;
        g_mn[(size_t)row * Oc + o] = mn;
    }

    __shared__ float sa[4][64], sb[4][64];
    sa[gg][o] = s1;
    sb[gg][o] = s2v;
    __syncthreads();
    if (gg == 0) {
        float t1 = sa[0][o] + sa[1][o] + sa[2][o] + sa[3][o];
        float t2 = sb[0][o] + sb[1][o] + sb[2][o] + sb[3][o];
        atomicAdd(&g_sum[o], (double)t1);
        atomicAdd(&g_sumsq[o], (double)t2);
    }
}

// -------------------- kernel: finalize BN affine --------------------
__global__ void k_fin(const float* __restrict__ gamma, const float* __restrict__ beta) {
    int o = threadIdx.x;
    const double cnt = (double)Bc * Nc * Kc;
    double mean = g_sum[o] / cnt;
    double var  = g_sumsq[o] / cnt - mean * mean;
    float a = gamma[o] * rsqrtf((float)var + BN_EPS);
    g_scale[o] = a;
    g_shift[o] = beta[o] - (float)mean * a;
}

// -------------------- kernel: apply affine + leaky + transpose to [B,O,N] --------------------
__global__ void __launch_bounds__(256) k_out(float* __restrict__ out) {
    int b  = blockIdx.y;
    int n0 = blockIdx.x * 64;
    __shared__ float sh[64][65];

    for (int t = threadIdx.x; t < 4096; t += 256) {
        int o  = t & 63;
        int nn = t >> 6;
        int row = b * Nc + n0 + nn;
        float a = g_scale[o];
        float m = (a >= 0.f) ? g_mx[(size_t)row * Oc + o] : g_mn[(size_t)row * Oc + o];
        float v = fmaf(a, m, g_shift[o]);
        v = (v >= 0.f) ? v : NEG_SLOPE * v;
        sh[o][nn] = v;
    }
    __syncthreads();
    for (int t = threadIdx.x; t < 4096; t += 256) {
        int nn = t & 63;
        int o  = t >> 6;
        out[((size_t)(b * Oc + o)) * Nc + n0 + nn] = sh[o][nn];
    }
}

// -------------------- launch --------------------
extern "C" void kernel_launch(void* const* d_in, const int* in_sizes, int n_in,
                              void* d_out, int out_size) {
    const float* x     = (const float*)d_in[0];   // [B, C, N]
    const float* W     = (const float*)d_in[1];   // [O, 2C]
    const float* gamma = (const float*)d_in[2];   // [O]
    const float* beta  = (const float*)d_in[3];   // [O]
    float* out = (float*)d_out;                   // [B, O, N]

    // keys[Kc][QB] u64 + As[Cc][AP] + Bs[Cc][BP] + sxxi[QB] + sxxj[TJ] + wf[QB]
    constexpr size_t KNN_SMEM =
        (size_t)(Kc * QB * 2 + Cc * AP + Cc * BP + QB + TJ + QB) * 4;

    static bool attr_set = false;
    if (!attr_set) {
        cudaFuncSetAttribute(k_knn8, cudaFuncAttributeMaxDynamicSharedMemorySize,
                             (int)KNN_SMEM);
        attr_set = true;
    }

    k_xx<<<(Bc * Nc) / 256, 256>>>(x);
    k_prep<<<16, 256>>>(W);
    k_pq<<<dim3(Nc / 32, Bc), 256>>>(x);
    k_knn8<<<dim3(Nc / QB, Bc), NT, KNN_SMEM>>>(x);
    k_edge<<<512, 256>>>();
    k_fin<<<1, Oc>>>(gamma, beta);
    k_out<<<dim3(Nc / 64, Bc), 256>>>(out);
}

// round 10
// speedup vs baseline: 1.9120x; 1.9120x over previous
#include <cuda_runtime.h>
#include <math.h>

// Problem constants
constexpr int Bc = 8;
constexpr int Cc = 64;
constexpr int Nc = 4096;
constexpr int Kc = 20;
constexpr int Oc = 64;
constexpr float BN_EPS = 1e-5f;
constexpr float NEG_SLOPE = 0.2f;
constexpr float FLT_BIG = 3.4e38f;

constexpr int TI = 128;      // queries per block
constexpr int TJ = 128;      // candidate tile size
constexpr int APAD = 132;    // padded row stride (floats)
constexpr int NT = 512;      // threads per block (knn)

// -------------------- device scratch (no allocations allowed) --------------------
__device__ float  g_xx[Bc * Nc];            // squared norms
__device__ int    g_idx[Bc * Nc * Kc];      // knn indices
__device__ float  g_P[Bc * Nc * Oc];        // W1 . x_j projection
__device__ float  g_Q[Bc * Nc * Oc];        // (W2-W1) . x_i projection
__device__ float  g_mx[Bc * Nc * Oc];       // max_k h
__device__ float  g_mn[Bc * Nc * Oc];       // min_k h
__device__ double g_sum[Oc];
__device__ double g_sumsq[Oc];
__device__ float  g_scale[Oc];
__device__ float  g_shift[Oc];
__device__ float  g_W1t[Cc * Oc];
__device__ float  g_Wdt[Cc * Oc];

// -------------------- f32x2 packed helpers --------------------
typedef unsigned long long u64;
typedef unsigned int u32;
__device__ __forceinline__ u64 dup2(float v) {
    u64 r; asm("mov.b64 %0, {%1, %1};" : "=l"(r) : "f"(v)); return r;
}
__device__ __forceinline__ void ffma2(u64& d, u64 a, u64 b) {
    asm("fma.rn.f32x2 %0, %1, %2, %0;" : "+l"(d) : "l"(a), "l"(b));
}
__device__ __forceinline__ u64 fma2o(u64 a, u64 b, u64 c) {
    u64 r; asm("fma.rn.f32x2 %0, %1, %2, %3;" : "=l"(r) : "l"(a), "l"(b), "l"(c));
    return r;
}
__device__ __forceinline__ u64 add2(u64 a, u64 b) {
    u64 r; asm("add.rn.f32x2 %0, %1, %2;" : "=l"(r) : "l"(a), "l"(b));
    return r;
}
// orderable float mapping: monotonic uint32 key (handles negatives)
__device__ __forceinline__ u32 ordf(float f) {
    u32 u = __float_as_uint(f);
    return (u & 0x80000000u) ? ~u : (u | 0x80000000u);
}
__device__ __forceinline__ float inv_ordf(u32 v) {
    u32 u = (v & 0x80000000u) ? ~v : (v | 0x80000000u);
    // inverse of ordf: if ordf set the sign bit, original was positive
    u = (v & 0x80000000u) ? (v & 0x7FFFFFFFu) : ~v;
    return __uint_as_float(u);
}

constexpr u64 KEY_MAX = 0xFFFFFFFFFFFFFFFFull;

// -------------------- kernel: squared norms --------------------
__global__ void k_xx(const float* __restrict__ x) {
    int t = blockIdx.x * blockDim.x + threadIdx.x;    // over B*N
    int b = t >> 12;
    int n = t & (Nc - 1);
    const float* xb = x + (size_t)b * Cc * Nc + n;
    float s = 0.f;
#pragma unroll
    for (int c = 0; c < Cc; ++c) {
        float v = xb[c * Nc];
        s = fmaf(v, v, s);
    }
    g_xx[t] = s;
}

// -------------------- kernel: prep W transposes + zero stats --------------------
__global__ void k_prep(const float* __restrict__ W) {
    int t = blockIdx.x * blockDim.x + threadIdx.x;
    if (t < Cc * Oc) {
        int c = t & 63;
        int o = t >> 6;
        float w1 = W[o * (2 * Cc) + c];
        float w2 = W[o * (2 * Cc) + Cc + c];
        g_W1t[c * Oc + o] = w1;
        g_Wdt[c * Oc + o] = w2 - w1;
    }
    if (blockIdx.x == 0 && t < Oc) {
        g_sum[t] = 0.0;
        g_sumsq[t] = 0.0;
    }
}

// -------------------- kernel: P and Q projections --------------------
__global__ void __launch_bounds__(256) k_pq(const float* __restrict__ x) {
    int b  = blockIdx.y;
    int n0 = blockIdx.x * 32;
    int o  = threadIdx.x & 63;
    int gg = threadIdx.x >> 6;
    __shared__ float xs[Cc][36];

    for (int t = threadIdx.x; t < Cc * 32; t += 256) {
        int nn = t & 31;
        int c  = t >> 5;
        xs[c][nn] = x[(size_t)b * Cc * Nc + c * Nc + n0 + nn];
    }
    __syncthreads();

    float ap[8], aq[8];
#pragma unroll
    for (int r = 0; r < 8; ++r) { ap[r] = 0.f; aq[r] = 0.f; }
    const int nbase = gg * 8;

#pragma unroll 8
    for (int c = 0; c < Cc; ++c) {
        float w1 = __ldg(&g_W1t[c * Oc + o]);
        float wd = __ldg(&g_Wdt[c * Oc + o]);
        float4 v0 = *(const float4*)&xs[c][nbase];
        float4 v1 = *(const float4*)&xs[c][nbase + 4];
        ap[0] = fmaf(w1, v0.x, ap[0]); aq[0] = fmaf(wd, v0.x, aq[0]);
        ap[1] = fmaf(w1, v0.y, ap[1]); aq[1] = fmaf(wd, v0.y, aq[1]);
        ap[2] = fmaf(w1, v0.z, ap[2]); aq[2] = fmaf(wd, v0.z, aq[2]);
        ap[3] = fmaf(w1, v0.w, ap[3]); aq[3] = fmaf(wd, v0.w, aq[3]);
        ap[4] = fmaf(w1, v1.x, ap[4]); aq[4] = fmaf(wd, v1.x, aq[4]);
        ap[5] = fmaf(w1, v1.y, ap[5]); aq[5] = fmaf(wd, v1.y, aq[5]);
        ap[6] = fmaf(w1, v1.z, ap[6]); aq[6] = fmaf(wd, v1.z, aq[6]);
        ap[7] = fmaf(w1, v1.w, ap[7]); aq[7] = fmaf(wd, v1.w, aq[7]);
    }

    int row0 = b * Nc + n0 + nbase;
#pragma unroll
    for (int r = 0; r < 8; ++r) {
        g_P[(size_t)(row0 + r) * Oc + o] = ap[r];
        g_Q[(size_t)(row0 + r) * Oc + o] = aq[r];
    }
}

// -------------------- scan insert (rare path): build key, insertion sort --------
__device__ __forceinline__ void insert_key(
    u64* keys, int tid, float d, int jg, float& worstf)
{
    u64 key = ((u64)ordf(d) << 32) | (u32)jg;
    int p = Kc - 1;
    while (p > 0) {
        u64 v = keys[(p - 1) * NT + tid];
        if (v < key) break;
        keys[p * NT + tid] = v;
        --p;
    }
    keys[p * NT + tid] = key;
    u32 hi = (u32)(keys[(Kc - 1) * NT + tid] >> 32);
    worstf = (hi == 0xFFFFFFFFu) ? FLT_BIG : inv_ordf(hi);
}

// -------------------- kernel: GEMM-tiled KNN v9 (R6 + float-first scan) ---------
// Identical structure to the proven k_knn5: 512 threads, 4i x 8j f32x2 tile,
// 128x128 block tile, keys in shared. ONLY the scan fast path changed: compare
// raw float vs register worstf; key build + u64 insert only on the rare qualify.
__global__ void __launch_bounds__(NT) k_knn9(const float* __restrict__ x) {
    extern __shared__ float sm[];
    u64*   keys = (u64*)sm;                        // [Kc][NT]
    float* As   = sm + (Kc * NT * 2);              // [Cc][APAD]
    float* Bs   = As + Cc * APAD;                  // [Cc][APAD]
    float* Ds   = Bs + Cc * APAD;                  // [TJ][APAD]
    float* sxxi = Ds + TJ * APAD;                  // [128]
    float* sxxj = sxxi + 128;                      // [128]

    const int tid = threadIdx.x;
    const int b   = blockIdx.y;
    const int i0  = blockIdx.x * TI;
    const float* xb = x + (size_t)b * Cc * Nc;

    const int ti = tid & 31;      // i-group (4 queries)
    const int tj = tid >> 5;      // j-group (8 candidates), warp-uniform
    const int qi = tid & 127;     // scan query
    const int qq = tid >> 7;      // scan quarter

    // load A tile: As[c][ii] = x[b][c][i0+ii]
    {
        int col = (tid & 31) * 4;
        int cb  = tid >> 5;
#pragma unroll
        for (int cc = 0; cc < 4; ++cc) {
            int c = cb + cc * 16;
            float4 v = *(const float4*)&xb[(size_t)c * Nc + i0 + col];
            *(float4*)&As[c * APAD + col] = v;
        }
    }
    if (tid < 128) sxxi[tid] = g_xx[b * Nc + i0 + tid];
#pragma unroll
    for (int kk = 0; kk < Kc; ++kk) keys[kk * NT + tid] = KEY_MAX;
    __syncthreads();

    // packed query norms for this thread's 2 i-pairs
    u64 xq[2];
    {
        ulonglong2 t0 = *(const ulonglong2*)&sxxi[ti * 4];
        xq[0] = t0.x; xq[1] = t0.y;
    }
    const u64 neg2 = dup2(-2.f);
    float worstf = FLT_BIG;

    for (int t = 0; t < Nc / TJ; ++t) {
        const int j0 = t * TJ;

        // load B tile global -> shared (overlaps with scan below)
        {
            int col = (tid & 31) * 4;
            int cb  = tid >> 5;
#pragma unroll
            for (int cc = 0; cc < 4; ++cc) {
                int c = cb + cc * 16;
                float4 v = *(const float4*)&xb[(size_t)c * Nc + j0 + col];
                *(float4*)&Bs[c * APAD + col] = v;
            }
        }
        if (tid < 128) sxxj[tid] = g_xx[b * Nc + j0 + tid];

        // scan previous tile's distances (float-first fast path)
        if (t > 0) {
            const int jp0 = j0 - TJ + qq * 32;
            const float* drow = &Ds[qq * 32 * APAD + qi];
#pragma unroll
            for (int jj = 0; jj < 32; ++jj) {
                float d = drow[jj * APAD];
                if (d < worstf) {
                    insert_key(keys, tid, d, jp0 + jj, worstf);
                }
            }
        }
        __syncthreads();   // B ready; Ds free for rewrite

        // ---- 4x8 f32x2 GEMM over c ----
        u64 acc[2][8];
#pragma unroll
        for (int ip = 0; ip < 2; ++ip)
#pragma unroll
            for (int j = 0; j < 8; ++j) acc[ip][j] = 0ULL;

#pragma unroll 4
        for (int c = 0; c < Cc; ++c) {
            ulonglong2 a01 = *(const ulonglong2*)&As[c * APAD + ti * 4];
            u64 ap0 = a01.x, ap1 = a01.y;
            float4 b0 = *(const float4*)&Bs[c * APAD + tj * 8];
            float4 b1 = *(const float4*)&Bs[c * APAD + tj * 8 + 4];
            u64 bd0 = dup2(b0.x), bd1 = dup2(b0.y), bd2 = dup2(b0.z), bd3 = dup2(b0.w);
            u64 bd4 = dup2(b1.x), bd5 = dup2(b1.y), bd6 = dup2(b1.z), bd7 = dup2(b1.w);
            ffma2(acc[0][0], ap0, bd0); ffma2(acc[1][0], ap1, bd0);
            ffma2(acc[0][1], ap0, bd1); ffma2(acc[1][1], ap1, bd1);
            ffma2(acc[0][2], ap0, bd2); ffma2(acc[1][2], ap1, bd2);
            ffma2(acc[0][3], ap0, bd3); ffma2(acc[1][3], ap1, bd3);
            ffma2(acc[0][4], ap0, bd4); ffma2(acc[1][4], ap1, bd4);
            ffma2(acc[0][5], ap0, bd5); ffma2(acc[1][5], ap1, bd5);
            ffma2(acc[0][6], ap0, bd6); ffma2(acc[1][6], ap1, bd6);
            ffma2(acc[0][7], ap0, bd7); ffma2(acc[1][7], ap1, bd7);
        }

        // epilogue: d = xxi + xxj - 2*inner (packed), store Ds[j][i]
#pragma unroll
        for (int j = 0; j < 8; ++j) {
            u64 xjd = dup2(sxxj[tj * 8 + j]);
            int row = (tj * 8 + j) * APAD + ti * 4;
#pragma unroll
            for (int ip = 0; ip < 2; ++ip) {
                u64 pre = add2(xq[ip], xjd);
                u64 d2  = fma2o(acc[ip][j], neg2, pre);
                *(u64*)&Ds[row + ip * 2] = d2;
            }
        }
        __syncthreads();   // Ds visible; Bs consumed
    }

    // scan last tile
    {
        const int jp0 = Nc - TJ + qq * 32;
        const float* drow = &Ds[qq * 32 * APAD + qi];
#pragma unroll
        for (int jj = 0; jj < 32; ++jj) {
            float d = drow[jj * APAD];
            if (d < worstf) {
                insert_key(keys, tid, d, jp0 + jj, worstf);
            }
        }
    }
    __syncthreads();

    // merge the 4 quarter lists per query (u64 order = dist, then idx)
    if (tid < 128) {
        u64 tk[Kc];
#pragma unroll
        for (int kk = 0; kk < Kc; ++kk) tk[kk] = KEY_MAX;
        for (int s = 0; s < 4; ++s) {
#pragma unroll 1
            for (int kk = 0; kk < Kc; ++kk) {
                u64 key = keys[kk * NT + s * 128 + tid];
                if (!(key < tk[Kc - 1])) break;   // source sorted ascending
                int p = Kc - 1;
                while (p > 0 && tk[p - 1] > key) {
                    tk[p] = tk[p - 1];
                    --p;
                }
                tk[p] = key;
            }
        }
        int* op = &g_idx[((size_t)(b * Nc + i0 + tid)) * Kc];
#pragma unroll
        for (int kk = 0; kk < Kc; ++kk) op[kk] = (int)(u32)(tk[kk] & 0xFFFFFFFFull);
    }
}

// -------------------- kernel: gather + max/min + BN stats --------------------
__global__ void __launch_bounds__(256) k_edge() {
    int o  = threadIdx.x & 63;
    int gg = threadIdx.x >> 6;
    float s1 = 0.f, s2v = 0.f;

    for (int row = blockIdx.x * 4 + gg; row < Bc * Nc; row += gridDim.x * 4) {
        int b  = row >> 12;
        int nb = b << 12;
        float qv = g_Q[(size_t)row * Oc + o];
        const int* ip = &g_idx[(size_t)row * Kc];
        float mx = -FLT_BIG, mn = FLT_BIG;
#pragma unroll
        for (int kk = 0; kk < Kc; ++kk) {
            int j = __ldg(&ip[kk]);
            float h = g_P[(size_t)(nb + j) * Oc + o] + qv;
            mx = fmaxf(mx, h);
            mn = fminf(mn, h);
            s1 += h;
            s2v = fmaf(h, h, s2v);
        }
        g_mx[(size_t)row * Oc + o] = mx;
        g_mn[(size_t)row * Oc + o] = mn;
    }

    __shared__ float sa[4][64], sb[4][64];
    sa[gg][o] = s1;
    sb[gg][o] = s2v;
    __syncthreads();
    if (gg == 0) {
        float t1 = sa[0][o] + sa[1][o] + sa[2][o] + sa[3][o];
        float t2 = sb[0][o] + sb[1][o] + sb[2][o] + sb[3][o];
        atomicAdd(&g_sum[o], (double)t1);
        atomicAdd(&g_sumsq[o], (double)t2);
    }
}

// -------------------- kernel: finalize BN affine --------------------
__global__ void k_fin(const float* __restrict__ gamma, const float* __restrict__ beta) {
    int o = threadIdx.x;
    const double cnt = (double)Bc * Nc * Kc;
    double mean = g_sum[o] / cnt;
    double var  = g_sumsq[o] / cnt - mean * mean;
    float a = gamma[o] * rsqrtf((float)var + BN_EPS);
    g_scale[o] = a;
    g_shift[o] = beta[o] - (float)mean * a;
}

// -------------------- kernel: apply affine + leaky + transpose to [B,O,N] --------------------
__global__ void __launch_bounds__(256) k_out(float* __restrict__ out) {
    int b  = blockIdx.y;
    int n0 = blockIdx.x * 64;
    __shared__ float sh[64][65];

    for (int t = threadIdx.x; t < 4096; t += 256) {
        int o  = t & 63;
        int nn = t >> 6;
        int row = b * Nc + n0 + nn;
        float a = g_scale[o];
        float m = (a >= 0.f) ? g_mx[(size_t)row * Oc + o] : g_mn[(size_t)row * Oc + o];
        float v = fmaf(a, m, g_shift[o]);
        v = (v >= 0.f) ? v : NEG_SLOPE * v;
        sh[o][nn] = v;
    }
    __syncthreads();
    for (int t = threadIdx.x; t < 4096; t += 256) {
        int nn = t & 63;
        int o  = t >> 6;
        out[((size_t)(b * Oc + o)) * Nc + n0 + nn] = sh[o][nn];
    }
}

// -------------------- launch --------------------
extern "C" void kernel_launch(void* const* d_in, const int* in_sizes, int n_in,
                              void* d_out, int out_size) {
    const float* x     = (const float*)d_in[0];   // [B, C, N]
    const float* W     = (const float*)d_in[1];   // [O, 2C]
    const float* gamma = (const float*)d_in[2];   // [O]
    const float* beta  = (const float*)d_in[3];   // [O]
    float* out = (float*)d_out;                   // [B, O, N]

    // keys [Kc][NT] u64 + As/Bs [Cc][APAD] + Ds [TJ][APAD] + sxx
    constexpr size_t KNN_SMEM =
        (size_t)Kc * NT * 8 +
        (size_t)(2 * Cc * APAD + TJ * APAD + 256) * 4;

    static bool attr_set = false;
    if (!attr_set) {
        cudaFuncSetAttribute(k_knn9, cudaFuncAttributeMaxDynamicSharedMemorySize,
                             (int)KNN_SMEM);
        attr_set = true;
    }

    k_xx<<<(Bc * Nc) / 256, 256>>>(x);
    k_prep<<<16, 256>>>(W);
    k_pq<<<dim3(Nc / 32, Bc), 256>>>(x);
    k_knn9<<<dim3(Nc / TI, Bc), NT, KNN_SMEM>>>(x);
    k_edge<<<512, 256>>>();
    k_fin<<<1, Oc>>>(gamma, beta);
    k_out<<<dim3(Nc / 64, Bc), 256>>>(out);
}

// round 11
// speedup vs baseline: 1.9132x; 1.0006x over previous
#include <cuda_runtime.h>
#include <math.h>

// Problem constants
constexpr int Bc = 8;
constexpr int Cc = 64;
constexpr int Nc = 4096;
constexpr int Kc = 20;
constexpr int Oc = 64;
constexpr float BN_EPS = 1e-5f;
constexpr float NEG_SLOPE = 0.2f;
constexpr float FLT_BIG = 3.4e38f;

constexpr int TI = 128;      // queries per block
constexpr int TJ = 128;      // candidate tile size
constexpr int APAD = 132;    // padded row stride (floats)
constexpr int NT = 512;      // threads per block (knn)

// -------------------- device scratch (no allocations allowed) --------------------
__device__ float  g_xx[Bc * Nc];            // squared norms
__device__ int    g_idx[Bc * Nc * Kc];      // knn indices
__device__ float  g_P[Bc * Nc * Oc];        // W1 . x_j projection
__device__ float  g_Q[Bc * Nc * Oc];        // (W2-W1) . x_i projection
__device__ float  g_mx[Bc * Nc * Oc];       // max_k h
__device__ float  g_mn[Bc * Nc * Oc];       // min_k h
__device__ double g_sum[Oc];
__device__ double g_sumsq[Oc];
__device__ float  g_scale[Oc];
__device__ float  g_shift[Oc];
__device__ float  g_W1t[Cc * Oc];
__device__ float  g_Wdt[Cc * Oc];

// -------------------- f32x2 packed helpers --------------------
typedef unsigned long long u64;
typedef unsigned int u32;
__device__ __forceinline__ u64 dup2(float v) {
    u64 r; asm("mov.b64 %0, {%1, %1};" : "=l"(r) : "f"(v)); return r;
}
__device__ __forceinline__ void ffma2(u64& d, u64 a, u64 b) {
    asm("fma.rn.f32x2 %0, %1, %2, %0;" : "+l"(d) : "l"(a), "l"(b));
}
__device__ __forceinline__ u64 fma2o(u64 a, u64 b, u64 c) {
    u64 r; asm("fma.rn.f32x2 %0, %1, %2, %3;" : "=l"(r) : "l"(a), "l"(b), "l"(c));
    return r;
}
__device__ __forceinline__ u64 add2(u64 a, u64 b) {
    u64 r; asm("add.rn.f32x2 %0, %1, %2;" : "=l"(r) : "l"(a), "l"(b));
    return r;
}
// orderable float mapping: monotonic uint32 key (handles negatives)
__device__ __forceinline__ u32 ordf(float f) {
    u32 u = __float_as_uint(f);
    return (u & 0x80000000u) ? ~u : (u | 0x80000000u);
}
__device__ __forceinline__ float inv_ordf(u32 v) {
    u32 u = (v & 0x80000000u) ? ~v : (v | 0x80000000u);
    // inverse of ordf: if ordf set the sign bit, original was positive
    u = (v & 0x80000000u) ? (v & 0x7FFFFFFFu) : ~v;
    return __uint_as_float(u);
}

constexpr u64 KEY_MAX = 0xFFFFFFFFFFFFFFFFull;

// -------------------- kernel: squared norms --------------------
__global__ void k_xx(const float* __restrict__ x) {
    int t = blockIdx.x * blockDim.x + threadIdx.x;    // over B*N
    int b = t >> 12;
    int n = t & (Nc - 1);
    const float* xb = x + (size_t)b * Cc * Nc + n;
    float s = 0.f;
#pragma unroll
    for (int c = 0; c < Cc; ++c) {
        float v = xb[c * Nc];
        s = fmaf(v, v, s);
    }
    g_xx[t] = s;
}

// -------------------- kernel: prep W transposes + zero stats --------------------
__global__ void k_prep(const float* __restrict__ W) {
    int t = blockIdx.x * blockDim.x + threadIdx.x;
    if (t < Cc * Oc) {
        int c = t & 63;
        int o = t >> 6;
        float w1 = W[o * (2 * Cc) + c];
        float w2 = W[o * (2 * Cc) + Cc + c];
        g_W1t[c * Oc + o] = w1;
        g_Wdt[c * Oc + o] = w2 - w1;
    }
    if (blockIdx.x == 0 && t < Oc) {
        g_sum[t] = 0.0;
        g_sumsq[t] = 0.0;
    }
}

// -------------------- kernel: P and Q projections --------------------
__global__ void __launch_bounds__(256) k_pq(const float* __restrict__ x) {
    int b  = blockIdx.y;
    int n0 = blockIdx.x * 32;
    int o  = threadIdx.x & 63;
    int gg = threadIdx.x >> 6;
    __shared__ float xs[Cc][36];

    for (int t = threadIdx.x; t < Cc * 32; t += 256) {
        int nn = t & 31;
        int c  = t >> 5;
        xs[c][nn] = x[(size_t)b * Cc * Nc + c * Nc + n0 + nn];
    }
    __syncthreads();

    float ap[8], aq[8];
#pragma unroll
    for (int r = 0; r < 8; ++r) { ap[r] = 0.f; aq[r] = 0.f; }
    const int nbase = gg * 8;

#pragma unroll 8
    for (int c = 0; c < Cc; ++c) {
        float w1 = __ldg(&g_W1t[c * Oc + o]);
        float wd = __ldg(&g_Wdt[c * Oc + o]);
        float4 v0 = *(const float4*)&xs[c][nbase];
        float4 v1 = *(const float4*)&xs[c][nbase + 4];
        ap[0] = fmaf(w1, v0.x, ap[0]); aq[0] = fmaf(wd, v0.x, aq[0]);
        ap[1] = fmaf(w1, v0.y, ap[1]); aq[1] = fmaf(wd, v0.y, aq[1]);
        ap[2] = fmaf(w1, v0.z, ap[2]); aq[2] = fmaf(wd, v0.z, aq[2]);
        ap[3] = fmaf(w1, v0.w, ap[3]); aq[3] = fmaf(wd, v0.w, aq[3]);
        ap[4] = fmaf(w1, v1.x, ap[4]); aq[4] = fmaf(wd, v1.x, aq[4]);
        ap[5] = fmaf(w1, v1.y, ap[5]); aq[5] = fmaf(wd, v1.y, aq[5]);
        ap[6] = fmaf(w1, v1.z, ap[6]); aq[6] = fmaf(wd, v1.z, aq[6]);
        ap[7] = fmaf(w1, v1.w, ap[7]); aq[7] = fmaf(wd, v1.w, aq[7]);
    }

    int row0 = b * Nc + n0 + nbase;
#pragma unroll
    for (int r = 0; r < 8; ++r) {
        g_P[(size_t)(row0 + r) * Oc + o] = ap[r];
        g_Q[(size_t)(row0 + r) * Oc + o] = aq[r];
    }
}

// -------------------- scan insert (rare path): build key, insertion sort --------
__device__ __forceinline__ void insert_key(
    u64* keys, int tid, float d, int jg, float& worstf)
{
    u64 key = ((u64)ordf(d) << 32) | (u32)jg;
    int p = Kc - 1;
    while (p > 0) {
        u64 v = keys[(p - 1) * NT + tid];
        if (v < key) break;
        keys[p * NT + tid] = v;
        --p;
    }
    keys[p * NT + tid] = key;
    u32 hi = (u32)(keys[(Kc - 1) * NT + tid] >> 32);
    worstf = (hi == 0xFFFFFFFFu) ? FLT_BIG : inv_ordf(hi);
}

// -------------------- kernel: GEMM-tiled KNN v9 (R6 + float-first scan) ---------
// Identical structure to the proven k_knn5: 512 threads, 4i x 8j f32x2 tile,
// 128x128 block tile, keys in shared. ONLY the scan fast path changed: compare
// raw float vs register worstf; key build + u64 insert only on the rare qualify.
__global__ void __launch_bounds__(NT) k_knn9(const float* __restrict__ x) {
    extern __shared__ float sm[];
    u64*   keys = (u64*)sm;                        // [Kc][NT]
    float* As   = sm + (Kc * NT * 2);              // [Cc][APAD]
    float* Bs   = As + Cc * APAD;                  // [Cc][APAD]
    float* Ds   = Bs + Cc * APAD;                  // [TJ][APAD]
    float* sxxi = Ds + TJ * APAD;                  // [128]
    float* sxxj = sxxi + 128;                      // [128]

    const int tid = threadIdx.x;
    const int b   = blockIdx.y;
    const int i0  = blockIdx.x * TI;
    const float* xb = x + (size_t)b * Cc * Nc;

    const int ti = tid & 31;      // i-group (4 queries)
    const int tj = tid >> 5;      // j-group (8 candidates), warp-uniform
    const int qi = tid & 127;     // scan query
    const int qq = tid >> 7;      // scan quarter

    // load A tile: As[c][ii] = x[b][c][i0+ii]
    {
        int col = (tid & 31) * 4;
        int cb  = tid >> 5;
#pragma unroll
        for (int cc = 0; cc < 4; ++cc) {
            int c = cb + cc * 16;
            float4 v = *(const float4*)&xb[(size_t)c * Nc + i0 + col];
            *(float4*)&As[c * APAD + col] = v;
        }
    }
    if (tid < 128) sxxi[tid] = g_xx[b * Nc + i0 + tid];
#pragma unroll
    for (int kk = 0; kk < Kc; ++kk) keys[kk * NT + tid] = KEY_MAX;
    __syncthreads();

    // packed query norms for this thread's 2 i-pairs
    u64 xq[2];
    {
        ulonglong2 t0 = *(const ulonglong2*)&sxxi[ti * 4];
        xq[0] = t0.x; xq[1] = t0.y;
    }
    const u64 neg2 = dup2(-2.f);
    float worstf = FLT_BIG;

    for (int t = 0; t < Nc / TJ; ++t) {
        const int j0 = t * TJ;

        // load B tile global -> shared (overlaps with scan below)
        {
            int col = (tid & 31) * 4;
            int cb  = tid >> 5;
#pragma unroll
            for (int cc = 0; cc < 4; ++cc) {
                int c = cb + cc * 16;
                float4 v = *(const float4*)&xb[(size_t)c * Nc + j0 + col];
                *(float4*)&Bs[c * APAD + col] = v;
            }
        }
        if (tid < 128) sxxj[tid] = g_xx[b * Nc + j0 + tid];

        // scan previous tile's distances (float-first fast path)
        if (t > 0) {
            const int jp0 = j0 - TJ + qq * 32;
            const float* drow = &Ds[qq * 32 * APAD + qi];
#pragma unroll
            for (int jj = 0; jj < 32; ++jj) {
                float d = drow[jj * APAD];
                if (d < worstf) {
                    insert_key(keys, tid, d, jp0 + jj, worstf);
                }
            }
        }
        __syncthreads();   // B ready; Ds free for rewrite

        // ---- 4x8 f32x2 GEMM over c ----
        u64 acc[2][8];
#pragma unroll
        for (int ip = 0; ip < 2; ++ip)
#pragma unroll
            for (int j = 0; j < 8; ++j) acc[ip][j] = 0ULL;

#pragma unroll 4
        for (int c = 0; c < Cc; ++c) {
            ulonglong2 a01 = *(const ulonglong2*)&As[c * APAD + ti * 4];
            u64 ap0 = a01.x, ap1 = a01.y;
            float4 b0 = *(const float4*)&Bs[c * APAD + tj * 8];
            float4 b1 = *(const float4*)&Bs[c * APAD + tj * 8 + 4];
            u64 bd0 = dup2(b0.x), bd1 = dup2(b0.y), bd2 = dup2(b0.z), bd3 = dup2(b0.w);
            u64 bd4 = dup2(b1.x), bd5 = dup2(b1.y), bd6 = dup2(b1.z), bd7 = dup2(b1.w);
            ffma2(acc[0][0], ap0, bd0); ffma2(acc[1][0], ap1, bd0);
            ffma2(acc[0][1], ap0, bd1); ffma2(acc[1][1], ap1, bd1);
            ffma2(acc[0][2], ap0, bd2); ffma2(acc[1][2], ap1, bd2);
            ffma2(acc[0][3], ap0, bd3); ffma2(acc[1][3], ap1, bd3);
            ffma2(acc[0][4], ap0, bd4); ffma2(acc[1][4], ap1, bd4);
            ffma2(acc[0][5], ap0, bd5); ffma2(acc[1][5], ap1, bd5);
            ffma2(acc[0][6], ap0, bd6); ffma2(acc[1][6], ap1, bd6);
            ffma2(acc[0][7], ap0, bd7); ffma2(acc[1][7], ap1, bd7);
        }

        // epilogue: d = xxi + xxj - 2*inner (packed), store Ds[j][i]
#pragma unroll
        for (int j = 0; j < 8; ++j) {
            u64 xjd = dup2(sxxj[tj * 8 + j]);
            int row = (tj * 8 + j) * APAD + ti * 4;
#pragma unroll
            for (int ip = 0; ip < 2; ++ip) {
                u64 pre = add2(xq[ip], xjd);
                u64 d2  = fma2o(acc[ip][j], neg2, pre);
                *(u64*)&Ds[row + ip * 2] = d2;
            }
        }
        __syncthreads();   // Ds visible; Bs consumed
    }

    // scan last tile
    {
        const int jp0 = Nc - TJ + qq * 32;
        const float* drow = &Ds[qq * 32 * APAD + qi];
#pragma unroll
        for (int jj = 0; jj < 32; ++jj) {
            float d = drow[jj * APAD];
            if (d < worstf) {
                insert_key(keys, tid, d, jp0 + jj, worstf);
            }
        }
    }
    __syncthreads();

    // merge the 4 quarter lists per query (u64 order = dist, then idx)
    if (tid < 128) {
        u64 tk[Kc];
#pragma unroll
        for (int kk = 0; kk < Kc; ++kk) tk[kk] = KEY_MAX;
        for (int s = 0; s < 4; ++s) {
#pragma unroll 1
            for (int kk = 0; kk < Kc; ++kk) {
                u64 key = keys[kk * NT + s * 128 + tid];
                if (!(key < tk[Kc - 1])) break;   // source sorted ascending
                int p = Kc - 1;
                while (p > 0 && tk[p - 1] > key) {
                    tk[p] = tk[p - 1];
                    --p;
                }
                tk[p] = key;
            }
        }
        int* op = &g_idx[((size_t)(b * Nc + i0 + tid)) * Kc];
#pragma unroll
        for (int kk = 0; kk < Kc; ++kk) op[kk] = (int)(u32)(tk[kk] & 0xFFFFFFFFull);
    }
}

// -------------------- kernel: gather + max/min + BN stats --------------------
__global__ void __launch_bounds__(256) k_edge() {
    int o  = threadIdx.x & 63;
    int gg = threadIdx.x >> 6;
    float s1 = 0.f, s2v = 0.f;

    for (int row = blockIdx.x * 4 + gg; row < Bc * Nc; row += gridDim.x * 4) {
        int b  = row >> 12;
        int nb = b << 12;
        float qv = g_Q[(size_t)row * Oc + o];
        const int* ip = &g_idx[(size_t)row * Kc];
        float mx = -FLT_BIG, mn = FLT_BIG;
#pragma unroll
        for (int kk = 0; kk < Kc; ++kk) {
            int j = __ldg(&ip[kk]);
            float h = g_P[(size_t)(nb + j) * Oc + o] + qv;
            mx = fmaxf(mx, h);
            mn = fminf(mn, h);
            s1 += h;
            s2v = fmaf(h, h, s2v);
        }
        g_mx[(size_t)row * Oc + o] = mx;
        g_mn[(size_t)row * Oc + o] = mn;
    }

    __shared__ float sa[4][64], sb[4][64];
    sa[gg][o] = s1;
    sb[gg][o] = s2v;
    __syncthreads();
    if (gg == 0) {
        float t1 = sa[0][o] + sa[1][o] + sa[2][o] + sa[3][o];
        float t2 = sb[0][o] + sb[1][o] + sb[2][o] + sb[3][o];
        atomicAdd(&g_sum[o], (double)t1);
        atomicAdd(&g_sumsq[o], (double)t2);
    }
}

// -------------------- kernel: finalize BN affine --------------------
__global__ void k_fin(const float* __restrict__ gamma, const float* __restrict__ beta) {
    int o = threadIdx.x;
    const double cnt = (double)Bc * Nc * Kc;
    double mean = g_sum[o] / cnt;
    double var  = g_sumsq[o] / cnt - mean * mean;
    float a = gamma[o] * rsqrtf((float)var + BN_EPS);
    g_scale[o] = a;
    g_shift[o] = beta[o] - (float)mean * a;
}

// -------------------- kernel: apply affine + leaky + transpose to [B,O,N] --------------------
__global__ void __launch_bounds__(256) k_out(float* __restrict__ out) {
    int b  = blockIdx.y;
    int n0 = blockIdx.x * 64;
    __shared__ float sh[64][65];

    for (int t = threadIdx.x; t < 4096; t += 256) {
        int o  = t & 63;
        int nn = t >> 6;
        int row = b * Nc + n0 + nn;
        float a = g_scale[o];
        float m = (a >= 0.f) ? g_mx[(size_t)row * Oc + o] : g_mn[(size_t)row * Oc + o];
        float v = fmaf(a, m, g_shift[o]);
        v = (v >= 0.f) ? v : NEG_SLOPE * v;
        sh[o][nn] = v;
    }
    __syncthreads();
    for (int t = threadIdx.x; t < 4096; t += 256) {
        int nn = t & 63;
        int o  = t >> 6;
        out[((size_t)(b * Oc + o)) * Nc + n0 + nn] = sh[o][nn];
    }
}

// -------------------- launch --------------------
extern "C" void kernel_launch(void* const* d_in, const int* in_sizes, int n_in,
                              void* d_out, int out_size) {
    const float* x     = (const float*)d_in[0];   // [B, C, N]
    const float* W     = (const float*)d_in[1];   // [O, 2C]
    const float* gamma = (const float*)d_in[2];   // [O]
    const float* beta  = (const float*)d_in[3];   // [O]
    float* out = (float*)d_out;                   // [B, O, N]

    // keys [Kc][NT] u64 + As/Bs [Cc][APAD] + Ds [TJ][APAD] + sxx
    constexpr size_t KNN_SMEM =
        (size_t)Kc * NT * 8 +
        (size_t)(2 * Cc * APAD + TJ * APAD + 256) * 4;

    static bool attr_set = false;
    if (!attr_set) {
        cudaFuncSetAttribute(k_knn9, cudaFuncAttributeMaxDynamicSharedMemorySize,
                             (int)KNN_SMEM);
        attr_set = true;
    }

    k_xx<<<(Bc * Nc) / 256, 256>>>(x);
    k_prep<<<16, 256>>>(W);
    k_pq<<<dim3(Nc / 32, Bc), 256>>>(x);
    k_knn9<<<dim3(Nc / TI, Bc), NT, KNN_SMEM>>>(x);
    k_edge<<<512, 256>>>();
    k_fin<<<1, Oc>>>(gamma, beta);
    k_out<<<dim3(Nc / 64, Bc), 256>>>(out);
}